// round 7
// baseline (speedup 1.0000x reference)
#include <cuda_runtime.h>
#include <cuda_fp16.h>

#define S_TOT 2048
#define B_DIM 64
#define N_DIM 256
#define EPSV 0.01f
#define INV_EPS 100.0f
#define THRESH 0.1f
#define MAX_ITER 100
#define LOG_EPS 1e-8f
#define THREADS 512
#define SPB 4           // samples per block

// E0_ij = exp((Cmin - C_ij)/eps) in fp16; row sums (of the fp16 values) in fp32.
__device__ __align__(16) __half g_E0h[B_DIM * N_DIM];
__device__ float g_logS[B_DIM];
__device__ float g_invS[B_DIM];
__device__ float g_Cmin;

// ---------------------------------------------------------------------------
// Init: 16 blocks x 256 threads. Every block computes cmin over all of C
// (identical deterministic reduction); block b then builds rows 4b..4b+3 of
// E0h and their row sums.
// ---------------------------------------------------------------------------
__global__ void __launch_bounds__(256) ot_init_kernel(const float* __restrict__ C) {
    __shared__ float sred[9];
    const int tid = threadIdx.x, l = tid & 31, w = tid >> 5;

    float mn = 3.402823466e38f;
    const float4* C4 = reinterpret_cast<const float4*>(C);
    #pragma unroll
    for (int k = 0; k < 16; k++) {
        const float4 c = C4[tid + 256 * k];
        mn = fminf(mn, fminf(fminf(c.x, c.y), fminf(c.z, c.w)));
    }
    #pragma unroll
    for (int o = 16; o; o >>= 1)
        mn = fminf(mn, __shfl_xor_sync(0xFFFFFFFFu, mn, o));
    if (l == 0) sred[w] = mn;
    __syncthreads();
    if (tid == 0) {
        float t = sred[0];
        #pragma unroll
        for (int k = 1; k < 8; k++) t = fminf(t, sred[k]);
        sred[8] = t;
        if (blockIdx.x == 0) g_Cmin = t;
    }
    __syncthreads();
    const float cmin = sred[8];

    #pragma unroll
    for (int rr = 0; rr < 4; rr++) {
        const int row = blockIdx.x * 4 + rr;
        const float val = __expf((cmin - C[(row << 8) + tid]) * INV_EPS);
        const __half hv = __float2half_rn(val);
        g_E0h[(row << 8) + tid] = hv;
        float f = __half2float(hv);
        #pragma unroll
        for (int o = 16; o; o >>= 1)
            f += __shfl_xor_sync(0xFFFFFFFFu, f, o);
        __syncthreads();
        if (l == 0) sred[w] = f;
        __syncthreads();
        if (tid == 0) {
            float s = 0.0f;
            #pragma unroll
            for (int k = 0; k < 8; k++) s += sred[k];
            g_logS[row] = __logf(s);
            g_invS[row] = 1.0f / s;
        }
    }
}

// smem layout (float offsets); E0h occupies floats [0,8192) as half[16384].
#define O_EUV  8192    // float[256]: euV[col][s] = eu_s(col)        (64 x float4)
#define O_EUW  8448    // float[256]: euW[col][s] = eu_s*mu_s(col)
#define O_SPA  8704    // float4[384]: partials, col a
#define O_SPB  10240   // float4[384]: partials, col b
#define O_SNU  11776   // 4 x 256: eps*log(nu)
#define O_SEV  12800   // 4 x 256: ev
#define O_SU   13824   // 4 x 64
#define O_SLM  14080   // 4 x 64
#define O_SMU  14336   // 4 x 64
#define O_SDU  14592   // 4 x 64
#define O_SRED 14848   // 4 x 16: [0..3]=mv partials, [8]=err, [9]=m_u, [10]=m_v
#define SMEM_FLOATS 14912

// ---------------------------------------------------------------------------
// Main: 4 samples / 512-thread block, one shared fp16 E0.
//  - it=0 u-update from precomputed row sums (no matrix pass).
//  - u-pass (it>=1): 4 warps per sample, 16 rows each (int4 = 8 halves/lane).
//  - v-pass: thread (qr = row-quarter, cp = col-pair). Light path (no sample
//    finishing): av-only, all 4 samples in one sweep. Full path (some sample
//    finishing): two sample-pair sweeps with av+ae; outputs written in-place.
// ---------------------------------------------------------------------------
extern "C" __global__ void __launch_bounds__(THREADS, 3)
ot_main_kernel(const float* __restrict__ mu,
               const float* __restrict__ nu,
               float* __restrict__ out) {
    extern __shared__ float sm[];
    __half* sE0h = reinterpret_cast<__half*>(sm);

    const int tid = threadIdx.x;
    const int l   = tid & 31;
    const int w   = tid >> 5;          // 0..15
    const int hs  = tid >> 7;          // sample slot for state / v row-quarter
    const int cp  = tid & 127;         // col-pair (v) / state lane
    const int hu  = w >> 2;            // u-pass sample
    const int wsu = w & 3;             // u-pass warp-within-sample
    const int sbase = blockIdx.x * SPB;

    // ---- stage E0h (32KB) ----
    {
        const uint4* g4 = reinterpret_cast<const uint4*>(g_E0h);
        uint4* s4 = reinterpret_cast<uint4*>(sE0h);
        #pragma unroll
        for (int k = 0; k < 4; k++)
            s4[tid + THREADS * k] = g4[tid + THREADS * k];
    }
    if (cp < B_DIM) {
        const float m = mu[(sbase + hs) * B_DIM + cp];
        sm[O_SMU + (hs << 6) + cp] = m;
        sm[O_SLM + (hs << 6) + cp] = __logf(m + LOG_EPS);
    }
    sm[O_SNU + (hs << 8) + cp]       = EPSV * __logf(nu[(sbase + hs) * N_DIM + cp] + LOG_EPS);
    sm[O_SNU + (hs << 8) + cp + 128] = EPSV * __logf(nu[(sbase + hs) * N_DIM + cp + 128] + LOG_EPS);
    const float cmin = g_Cmin;
    __syncthreads();

    bool act[SPB] = {true, true, true, true};

    for (int it = 0; it < MAX_ITER; ++it) {
        // ================= u phase =================
        if (it == 0) {
            if (cp < B_DIM) {
                const float u1 = EPSV * (sm[O_SLM + (hs << 6) + cp] - g_logS[cp]) + cmin;
                sm[O_SU  + (hs << 6) + cp] = u1;
                sm[O_SDU + (hs << 6) + cp] = fabsf(u1);
            }
        } else if (act[hu]) {
            const float m_v = sm[O_SRED + (hu << 4) + 10];
            const float4* sev4 = reinterpret_cast<const float4*>(sm + O_SEV + (hu << 8));
            const float4 evA = sev4[2 * l], evB = sev4[2 * l + 1];
            #pragma unroll
            for (int r = 0; r < 16; ++r) {
                const int row = (wsu << 4) + r;
                const int4 hv = reinterpret_cast<const int4*>(sE0h + (row << 8))[l];
                const __half2* hp = reinterpret_cast<const __half2*>(&hv);
                const float2 f0 = __half22float2(hp[0]);
                const float2 f1 = __half22float2(hp[1]);
                const float2 f2 = __half22float2(hp[2]);
                const float2 f3 = __half22float2(hp[3]);
                float p = f0.x * evA.x + f0.y * evA.y + f1.x * evA.z + f1.y * evA.w
                        + f2.x * evB.x + f2.y * evB.y + f3.x * evB.z + f3.y * evB.w;
                #pragma unroll
                for (int o = 16; o; o >>= 1)
                    p += __shfl_xor_sync(0xFFFFFFFFu, p, o);
                if (l == r) {
                    const float unew = EPSV * sm[O_SLM + (hu << 6) + row]
                                     - (m_v - cmin) - EPSV * __logf(p);
                    sm[O_SDU + (hu << 6) + row] = fabsf(unew - sm[O_SU + (hu << 6) + row]);
                    sm[O_SU  + (hu << 6) + row] = unew;
                }
            }
        }
        __syncthreads();                                        // B1

        // ---- err / m_u reduce: warp s handles sample s ----
        if (w < SPB) {
            const float* sduW = sm + O_SDU + (w << 6);
            const float* suW  = sm + O_SU  + (w << 6);
            float d  = sduW[l] + sduW[l + 32];
            float um = fmaxf(suW[l], suW[l + 32]);
            #pragma unroll
            for (int o = 16; o; o >>= 1) {
                d  += __shfl_xor_sync(0xFFFFFFFFu, d, o);
                um  = fmaxf(um, __shfl_xor_sync(0xFFFFFFFFu, um, o));
            }
            if (l == 0) { sm[O_SRED + (w << 4) + 8] = d; sm[O_SRED + (w << 4) + 9] = um; }
        }
        __syncthreads();                                        // B2

        bool last[SPB];
        bool anyLast = false;
        #pragma unroll
        for (int s2 = 0; s2 < SPB; s2++) {
            last[s2] = act[s2] && (sm[O_SRED + (s2 << 4) + 8] < THRESH || it == MAX_ITER - 1);
            anyLast |= last[s2];
        }

        // ---- euV/euW: per row, per sample ----
        if (cp < B_DIM && act[hs]) {
            const float eu = (it == 0)
                ? (sm[O_SMU + (hs << 6) + cp] + LOG_EPS) * g_invS[cp]
                : __expf((sm[O_SU + (hs << 6) + cp] - sm[O_SRED + (hs << 4) + 9]) * INV_EPS);
            sm[O_EUV + (cp << 2) + hs] = eu;
            sm[O_EUW + (cp << 2) + hs] = eu * sm[O_SMU + (hs << 6) + cp];
        }
        __syncthreads();                                        // B3

        const int qr = hs;                 // row-quarter for v-pass
        const __half2* cph = reinterpret_cast<const __half2*>(sE0h) + (qr << 11) + cp;
        float4* spA = reinterpret_cast<float4*>(sm + O_SPA);
        float4* spB = reinterpret_cast<float4*>(sm + O_SPB);

        if (!anyLast) {
            // ========== LIGHT v-pass: av only, 4 samples, one sweep ==========
            float va0 = 0, va1 = 0, va2 = 0, va3 = 0;
            float vb0 = 0, vb1 = 0, vb2 = 0, vb3 = 0;
            const float4* euV4 = reinterpret_cast<const float4*>(sm + O_EUV) + (qr << 4);
            #pragma unroll
            for (int i = 0; i < 16; i++) {
                const float2 cf = __half22float2(cph[i << 7]);
                const float4 q  = euV4[i];
                va0 = fmaf(cf.x, q.x, va0); vb0 = fmaf(cf.y, q.x, vb0);
                va1 = fmaf(cf.x, q.y, va1); vb1 = fmaf(cf.y, q.y, vb1);
                va2 = fmaf(cf.x, q.z, va2); vb2 = fmaf(cf.y, q.z, vb2);
                va3 = fmaf(cf.x, q.w, va3); vb3 = fmaf(cf.y, q.w, vb3);
            }
            if (qr) {
                spA[((qr - 1) << 7) + cp] = make_float4(va0, va1, va2, va3);
                spB[((qr - 1) << 7) + cp] = make_float4(vb0, vb1, vb2, vb3);
            }
            __syncthreads();                                    // B4
            float v_a[SPB], v_b[SPB];
            if (qr == 0) {
                #pragma unroll
                for (int t = 0; t < 3; t++) {
                    const float4 pa = spA[(t << 7) + cp];
                    const float4 pb = spB[(t << 7) + cp];
                    va0 += pa.x; va1 += pa.y; va2 += pa.z; va3 += pa.w;
                    vb0 += pb.x; vb1 += pb.y; vb2 += pb.z; vb3 += pb.w;
                }
                const float av[SPB] = {va0, va1, va2, va3};
                const float bv[SPB] = {vb0, vb1, vb2, vb3};
                #pragma unroll
                for (int s2 = 0; s2 < SPB; s2++) {
                    const float2 ln = *reinterpret_cast<const float2*>(
                        sm + O_SNU + (s2 << 8) + 2 * cp);
                    const float mue = (it == 0) ? cmin : sm[O_SRED + (s2 << 4) + 9];
                    v_a[s2] = ln.x - (mue - cmin) - EPSV * __logf(av[s2]);
                    v_b[s2] = ln.y - (mue - cmin) - EPSV * __logf(bv[s2]);
                    float m = fmaxf(v_a[s2], v_b[s2]);
                    #pragma unroll
                    for (int o = 16; o; o >>= 1)
                        m = fmaxf(m, __shfl_xor_sync(0xFFFFFFFFu, m, o));
                    if (l == 0) sm[O_SRED + (s2 << 4) + w] = m;   // w = 0..3
                }
            }
            __syncthreads();                                    // B5
            if (qr == 0) {
                #pragma unroll
                for (int s2 = 0; s2 < SPB; s2++) {
                    if (!act[s2]) continue;
                    const float* r = sm + O_SRED + (s2 << 4);
                    const float m = fmaxf(fmaxf(r[0], r[1]), fmaxf(r[2], r[3]));
                    const float ea = __expf((v_a[s2] - m) * INV_EPS);
                    const float eb = __expf((v_b[s2] - m) * INV_EPS);
                    *reinterpret_cast<float2*>(sm + O_SEV + (s2 << 8) + 2 * cp)
                        = make_float2(ea, eb);
                    if (tid == 0) sm[O_SRED + (s2 << 4) + 10] = m;
                }
            }
            __syncthreads();                                    // B6
        } else {
            // ========== FULL v-pass: two sample-pair sweeps, av+ae ==========
            #pragma unroll
            for (int p = 0; p < 2; p++) {
                const int sA = 2 * p, sB = 2 * p + 1;
                float vaA = 0, vbA = 0, eaA = 0, ebA = 0;
                float vaB = 0, vbB = 0, eaB = 0, ebB = 0;
                {
                    const float4* euV4 = reinterpret_cast<const float4*>(sm + O_EUV) + (qr << 4);
                    const float4* euW4 = reinterpret_cast<const float4*>(sm + O_EUW) + (qr << 4);
                    #pragma unroll
                    for (int i = 0; i < 16; i++) {
                        const float2 cf = __half22float2(cph[i << 7]);
                        const float4 qv = euV4[i];
                        const float4 qw = euW4[i];
                        const float euA_ = p ? qv.z : qv.x;
                        const float euB_ = p ? qv.w : qv.y;
                        const float wtA_ = p ? qw.z : qw.x;
                        const float wtB_ = p ? qw.w : qw.y;
                        vaA = fmaf(cf.x, euA_, vaA); vbA = fmaf(cf.y, euA_, vbA);
                        eaA = fmaf(cf.x, wtA_, eaA); ebA = fmaf(cf.y, wtA_, ebA);
                        vaB = fmaf(cf.x, euB_, vaB); vbB = fmaf(cf.y, euB_, vbB);
                        eaB = fmaf(cf.x, wtB_, eaB); ebB = fmaf(cf.y, wtB_, ebB);
                    }
                }
                if (qr) {
                    spA[((qr - 1) << 7) + cp] = make_float4(vaA, eaA, vaB, eaB);
                    spB[((qr - 1) << 7) + cp] = make_float4(vbA, ebA, vbB, ebB);
                }
                __syncthreads();                                // B4p
                float vA_a = 0, vA_b = 0, vB_a = 0, vB_b = 0;
                if (qr == 0) {
                    #pragma unroll
                    for (int t = 0; t < 3; t++) {
                        const float4 pa = spA[(t << 7) + cp];
                        const float4 pb = spB[(t << 7) + cp];
                        vaA += pa.x; eaA += pa.y; vaB += pa.z; eaB += pa.w;
                        vbA += pb.x; ebA += pb.y; vbB += pb.z; ebB += pb.w;
                    }
                    const float2 lnA = *reinterpret_cast<const float2*>(
                        sm + O_SNU + (sA << 8) + 2 * cp);
                    const float2 lnB = *reinterpret_cast<const float2*>(
                        sm + O_SNU + (sB << 8) + 2 * cp);
                    const float mueA = (it == 0) ? cmin : sm[O_SRED + (sA << 4) + 9];
                    const float mueB = (it == 0) ? cmin : sm[O_SRED + (sB << 4) + 9];
                    vA_a = lnA.x - (mueA - cmin) - EPSV * __logf(vaA);
                    vA_b = lnA.y - (mueA - cmin) - EPSV * __logf(vbA);
                    vB_a = lnB.x - (mueB - cmin) - EPSV * __logf(vaB);
                    vB_b = lnB.y - (mueB - cmin) - EPSV * __logf(vbB);
                    float mA = fmaxf(vA_a, vA_b);
                    float mB = fmaxf(vB_a, vB_b);
                    #pragma unroll
                    for (int o = 16; o; o >>= 1) {
                        mA = fmaxf(mA, __shfl_xor_sync(0xFFFFFFFFu, mA, o));
                        mB = fmaxf(mB, __shfl_xor_sync(0xFFFFFFFFu, mB, o));
                    }
                    if (l == 0) {
                        sm[O_SRED + (sA << 4) + w] = mA;
                        sm[O_SRED + (sB << 4) + w] = mB;
                    }
                }
                __syncthreads();                                // B5p
                if (qr == 0) {
                    const float* rA = sm + O_SRED + (sA << 4);
                    const float* rB = sm + O_SRED + (sB << 4);
                    const float mA = fmaxf(fmaxf(rA[0], rA[1]), fmaxf(rA[2], rA[3]));
                    const float mB = fmaxf(fmaxf(rB[0], rB[1]), fmaxf(rB[2], rB[3]));
                    if (act[sA]) {
                        const float ea = __expf((vA_a - mA) * INV_EPS);
                        const float eb = __expf((vA_b - mA) * INV_EPS);
                        *reinterpret_cast<float2*>(sm + O_SEV + (sA << 8) + 2 * cp)
                            = make_float2(ea, eb);
                        if (tid == 0) sm[O_SRED + (sA << 4) + 10] = mA;
                        if (last[sA]) {
                            const float mueA = (it == 0) ? cmin : sm[O_SRED + (sA << 4) + 9];
                            const float sc = __expf((mueA + mA - cmin) * INV_EPS);
                            *reinterpret_cast<float2*>(out + (sbase + sA) * N_DIM + 2 * cp)
                                = make_float2(sc * ea * eaA, sc * eb * ebA);
                        }
                    }
                    if (act[sB]) {
                        const float ea = __expf((vB_a - mB) * INV_EPS);
                        const float eb = __expf((vB_b - mB) * INV_EPS);
                        *reinterpret_cast<float2*>(sm + O_SEV + (sB << 8) + 2 * cp)
                            = make_float2(ea, eb);
                        if (tid == 0) sm[O_SRED + (sB << 4) + 10] = mB;
                        if (last[sB]) {
                            const float mueB = (it == 0) ? cmin : sm[O_SRED + (sB << 4) + 9];
                            const float sc = __expf((mueB + mB - cmin) * INV_EPS);
                            *reinterpret_cast<float2*>(out + (sbase + sB) * N_DIM + 2 * cp)
                                = make_float2(sc * ea * eaB, sc * eb * ebB);
                        }
                    }
                }
                __syncthreads();                                // B6p
            }
        }

        bool more = false;
        #pragma unroll
        for (int s2 = 0; s2 < SPB; s2++) {
            if (last[s2]) act[s2] = false;
            more |= act[s2];
        }
        if (!more) break;
    }
}

// ---------------------------------------------------------------------------
// Launch
// ---------------------------------------------------------------------------
extern "C" void kernel_launch(void* const* d_in, const int* in_sizes, int n_in,
                              void* d_out, int out_size) {
    const float* mu = nullptr;
    const float* nu = nullptr;
    const float* C  = nullptr;
    for (int i = 0; i < n_in; ++i) {
        if (in_sizes[i] == S_TOT * B_DIM)      mu = (const float*)d_in[i];
        else if (in_sizes[i] == S_TOT * N_DIM) nu = (const float*)d_in[i];
        else if (in_sizes[i] == B_DIM * N_DIM) C  = (const float*)d_in[i];
    }
    float* out = (float*)d_out;

    const int smem_bytes = SMEM_FLOATS * sizeof(float);   // ~58.3 KB
    cudaFuncSetAttribute(ot_main_kernel,
                         cudaFuncAttributeMaxDynamicSharedMemorySize, smem_bytes);

    ot_init_kernel<<<16, 256>>>(C);
    ot_main_kernel<<<S_TOT / SPB, THREADS, smem_bytes>>>(mu, nu, out);
}

// round 8
// speedup vs baseline: 1.6000x; 1.6000x over previous
#include <cuda_runtime.h>
#include <cuda_fp16.h>

#define S_TOT 2048
#define B_DIM 64
#define N_DIM 256
#define EPSV 0.01f
#define INV_EPS 100.0f
#define THRESH 0.1f
#define MAX_ITER 100
#define LOG_EPS 1e-8f
#define THREADS 512

// E0_ij = exp((Cmin - C_ij)/eps) in fp16; row sums (of fp16 values) in fp32.
__device__ __align__(16) __half g_E0h[B_DIM * N_DIM];
__device__ float g_logS[B_DIM];
__device__ float g_invS[B_DIM];
__device__ float g_Cmin;

// ---------------------------------------------------------------------------
// Init: 16 blocks x 256 threads. Every block redundantly computes cmin
// (identical deterministic reduction); block b builds rows 4b..4b+3.
// ---------------------------------------------------------------------------
__global__ void __launch_bounds__(256) ot_init_kernel(const float* __restrict__ C) {
    __shared__ float sred[9];
    const int tid = threadIdx.x, l = tid & 31, w = tid >> 5;

    float mn = 3.402823466e38f;
    const float4* C4 = reinterpret_cast<const float4*>(C);
    #pragma unroll
    for (int k = 0; k < 16; k++) {
        const float4 c = C4[tid + 256 * k];
        mn = fminf(mn, fminf(fminf(c.x, c.y), fminf(c.z, c.w)));
    }
    #pragma unroll
    for (int o = 16; o; o >>= 1)
        mn = fminf(mn, __shfl_xor_sync(0xFFFFFFFFu, mn, o));
    if (l == 0) sred[w] = mn;
    __syncthreads();
    if (tid == 0) {
        float t = sred[0];
        #pragma unroll
        for (int k = 1; k < 8; k++) t = fminf(t, sred[k]);
        sred[8] = t;
        if (blockIdx.x == 0) g_Cmin = t;
    }
    __syncthreads();
    const float cmin = sred[8];

    #pragma unroll
    for (int rr = 0; rr < 4; rr++) {
        const int row = blockIdx.x * 4 + rr;
        const float val = __expf((cmin - C[(row << 8) + tid]) * INV_EPS);
        const __half hv = __float2half_rn(val);
        g_E0h[(row << 8) + tid] = hv;
        float f = __half2float(hv);
        #pragma unroll
        for (int o = 16; o; o >>= 1)
            f += __shfl_xor_sync(0xFFFFFFFFu, f, o);
        __syncthreads();
        if (l == 0) sred[w] = f;
        __syncthreads();
        if (tid == 0) {
            float s = 0.0f;
            #pragma unroll
            for (int k = 0; k < 8; k++) s += sred[k];
            g_logS[row] = __logf(s);
            g_invS[row] = 1.0f / s;
        }
    }
}

// smem layout (float offsets); E0h occupies floats [0,8192) as half[16384].
#define O_EUWT  8192    // float4[64]: (eu0, wt0, eu1, wt1)
#define O_SPART 8448    // spartA float4[384] @8448, spartB float4[384] @9984
#define O_SDU   8448    // alias (temporally disjoint)
#define O_SNU   11520   // snu0 [256], snu1 [256]
#define O_SEV   12032   // sev0 [256], sev1 [256]
#define O_SU    12544   // 2 x 64
#define O_SLM   12672
#define O_SMU   12800
#define O_SRED  12928   // 2 x 16: [0..3]=mv partials, [8]=err, [9]=m_u, [10]=m_v
#define SMEM_FLOATS 12960

// ---------------------------------------------------------------------------
// Main (R6 architecture): 2 samples/block, 512 threads, fp16 E0 in shared,
// 4 blocks/SM (2048 threads = full occupancy).
//  - it=0 u-update from precomputed row sums.
//  - u-pass (it>=1): per-sample; warps 0-7 sample0, 8-15 sample1.
//  - v-pass: thread (qr = row-quarter, cp = col-pair). LIGHT path (no sample
//    finishing): av-only, 4 FMAs/row, single-float4 exchange. FULL path:
//    av+ae, outputs written in place (R6 code).
// ---------------------------------------------------------------------------
extern "C" __global__ void __launch_bounds__(THREADS, 4)
ot_main_kernel(const float* __restrict__ mu,
               const float* __restrict__ nu,
               float* __restrict__ out) {
    extern __shared__ float sm[];
    __half* sE0h = reinterpret_cast<__half*>(sm);

    const int tid = threadIdx.x;
    const int h   = tid >> 8;          // sample slot (u/euwt mapping)
    const int col = tid & 255;
    const int l   = tid & 31;
    const int w   = tid >> 5;          // 0..15
    const int ws  = w & 7;
    const int qr  = tid >> 7;          // row-quarter (v mapping)
    const int cp  = tid & 127;         // col-pair

    float* snu0   = sm + O_SNU;
    float* snu1   = sm + O_SNU + 256;
    float* sev_h  = sm + O_SEV + (h << 8);
    float* su_h   = sm + O_SU  + (h << 6);
    float* slm_h  = sm + O_SLM + (h << 6);
    float* smu_h  = sm + O_SMU + (h << 6);
    float* sred0  = sm + O_SRED;
    float* sred1  = sm + O_SRED + 16;
    float* sred_h = sm + O_SRED + (h << 4);
    float* sdu_h  = sm + O_SDU + (h << 6);
    float4* spartA = reinterpret_cast<float4*>(sm + O_SPART);
    float4* spartB = spartA + 384;

    const int s0 = blockIdx.x * 2, s1 = s0 + 1, s_h = s0 + h;

    // ---- stage E0h (32KB, uint4) ----
    {
        const uint4* g4 = reinterpret_cast<const uint4*>(g_E0h);
        uint4* s4 = reinterpret_cast<uint4*>(sE0h);
        #pragma unroll
        for (int k = 0; k < 4; k++)
            s4[tid + THREADS * k] = g4[tid + THREADS * k];
    }
    if (col < B_DIM) {
        const float m = mu[s_h * B_DIM + col];
        smu_h[col] = m;
        slm_h[col] = __logf(m + LOG_EPS);
    }
    sm[O_SNU + (h << 8) + col] = EPSV * __logf(nu[s_h * N_DIM + col] + LOG_EPS);
    if (tid == 0) { sred0[10] = 0.0f; sred1[10] = 0.0f; }
    const float cmin = g_Cmin;
    __syncthreads();

    bool active0 = true, active1 = true;

    for (int it = 0; it < MAX_ITER; ++it) {
        const bool act_h = h ? active1 : active0;

        // ---- u phase ----
        if (it == 0) {
            if (col < B_DIM) {
                const float u1 = EPSV * (slm_h[col] - g_logS[col]) + cmin;
                su_h[col]  = u1;
                sdu_h[col] = fabsf(u1);
            }
        } else if (act_h) {
            const float m_v_h = sred_h[10];
            const float4 evA = reinterpret_cast<const float4*>(sev_h)[2 * l];
            const float4 evB = reinterpret_cast<const float4*>(sev_h)[2 * l + 1];
            #pragma unroll
            for (int r = 0; r < 8; ++r) {
                const int row = (ws << 3) + r;
                const int4 hv = reinterpret_cast<const int4*>(sE0h + (row << 8))[l];
                const __half2* hp = reinterpret_cast<const __half2*>(&hv);
                const float2 f0 = __half22float2(hp[0]);
                const float2 f1 = __half22float2(hp[1]);
                const float2 f2 = __half22float2(hp[2]);
                const float2 f3 = __half22float2(hp[3]);
                float p = f0.x * evA.x + f0.y * evA.y + f1.x * evA.z + f1.y * evA.w
                        + f2.x * evB.x + f2.y * evB.y + f3.x * evB.z + f3.y * evB.w;
                #pragma unroll
                for (int o = 16; o; o >>= 1)
                    p += __shfl_xor_sync(0xFFFFFFFFu, p, o);
                if (l == r) {
                    const float unew = EPSV * slm_h[row] - (m_v_h - cmin)
                                     - EPSV * __logf(p);
                    sdu_h[row] = fabsf(unew - su_h[row]);
                    su_h[row]  = unew;
                }
            }
        }
        __syncthreads();                                        // B1

        // ---- err / m_u reduce (warps 0 and 8) ----
        if (ws == 0) {
            float d  = sdu_h[l] + sdu_h[l + 32];
            float um = fmaxf(su_h[l], su_h[l + 32]);
            #pragma unroll
            for (int o = 16; o; o >>= 1) {
                d  += __shfl_xor_sync(0xFFFFFFFFu, d, o);
                um  = fmaxf(um, __shfl_xor_sync(0xFFFFFFFFu, um, o));
            }
            if (l == 0) { sred_h[8] = d; sred_h[9] = um; }
        }
        __syncthreads();                                        // B2
        const float err0 = sred0[8], err1 = sred1[8];
        const bool last0 = active0 && (err0 < THRESH || it == MAX_ITER - 1);
        const bool last1 = active1 && (err1 < THRESH || it == MAX_ITER - 1);
        const bool anyLast = last0 || last1;

        // ---- euwt: (eu0, wt0, eu1, wt1) per row ----
        if (col < B_DIM && act_h) {
            const float eu = (it == 0)
                ? (smu_h[col] + LOG_EPS) * g_invS[col]
                : __expf((su_h[col] - sred_h[9]) * INV_EPS);
            float* qp = sm + O_EUWT + (col << 2);
            qp[2 * h]     = eu;
            qp[2 * h + 1] = eu * smu_h[col];
        }
        __syncthreads();                                        // B3

        const __half2* cph = reinterpret_cast<const __half2*>(sE0h)
                           + (qr << 11) + cp;
        const float4* qw = reinterpret_cast<const float4*>(sm + O_EUWT) + (qr << 4);

        if (!anyLast) {
            // ===== LIGHT v-pass: av only (4 FMAs/row), 1-float4 exchange =====
            float av0a = 0, av0b = 0, av1a = 0, av1b = 0;
            #pragma unroll
            for (int i = 0; i < 16; i++) {
                const float2 cf = __half22float2(cph[i << 7]);
                const float4 q  = qw[i];
                av0a = fmaf(cf.x, q.x, av0a); av0b = fmaf(cf.y, q.x, av0b);
                av1a = fmaf(cf.x, q.z, av1a); av1b = fmaf(cf.y, q.z, av1b);
            }
            if (qr) spartA[((qr - 1) << 7) + cp] = make_float4(av0a, av0b, av1a, av1b);
            __syncthreads();                                    // B4
            float v0a = 0, v0b = 0, v1a = 0, v1b = 0, m0 = 0, m1 = 0;
            if (qr == 0) {
                #pragma unroll
                for (int t = 0; t < 3; t++) {
                    const float4 pa = spartA[(t << 7) + cp];
                    av0a += pa.x; av0b += pa.y; av1a += pa.z; av1b += pa.w;
                }
                const float2 ln0 = *reinterpret_cast<const float2*>(snu0 + 2 * cp);
                const float2 ln1 = *reinterpret_cast<const float2*>(snu1 + 2 * cp);
                const float mue0 = (it == 0) ? cmin : sred0[9];
                const float mue1 = (it == 0) ? cmin : sred1[9];
                v0a = ln0.x - (mue0 - cmin) - EPSV * __logf(av0a);
                v0b = ln0.y - (mue0 - cmin) - EPSV * __logf(av0b);
                v1a = ln1.x - (mue1 - cmin) - EPSV * __logf(av1a);
                v1b = ln1.y - (mue1 - cmin) - EPSV * __logf(av1b);
                m0 = fmaxf(v0a, v0b);
                m1 = fmaxf(v1a, v1b);
                #pragma unroll
                for (int o = 16; o; o >>= 1) {
                    m0 = fmaxf(m0, __shfl_xor_sync(0xFFFFFFFFu, m0, o));
                    m1 = fmaxf(m1, __shfl_xor_sync(0xFFFFFFFFu, m1, o));
                }
                if (l == 0) { sred0[w] = m0; sred1[w] = m1; }   // w = 0..3
            }
            __syncthreads();                                    // B5
            if (qr == 0) {
                m0 = fmaxf(fmaxf(sred0[0], sred0[1]), fmaxf(sred0[2], sred0[3]));
                m1 = fmaxf(fmaxf(sred1[0], sred1[1]), fmaxf(sred1[2], sred1[3]));
                if (active0) {
                    *reinterpret_cast<float2*>(sm + O_SEV + 2 * cp)
                        = make_float2(__expf((v0a - m0) * INV_EPS),
                                      __expf((v0b - m0) * INV_EPS));
                    if (tid == 0) sred0[10] = m0;
                }
                if (active1) {
                    *reinterpret_cast<float2*>(sm + O_SEV + 256 + 2 * cp)
                        = make_float2(__expf((v1a - m1) * INV_EPS),
                                      __expf((v1b - m1) * INV_EPS));
                    if (tid == 0) sred1[10] = m1;
                }
            }
            __syncthreads();                                    // B6
        } else {
            // ===== FULL v-pass: av+ae, outputs written on last iteration =====
            float av0a = 0, av0b = 0, ae0a = 0, ae0b = 0;
            float av1a = 0, av1b = 0, ae1a = 0, ae1b = 0;
            #pragma unroll
            for (int i = 0; i < 16; i++) {
                const float2 cf = __half22float2(cph[i << 7]);
                const float4 q  = qw[i];
                av0a = fmaf(cf.x, q.x, av0a); av0b = fmaf(cf.y, q.x, av0b);
                ae0a = fmaf(cf.x, q.y, ae0a); ae0b = fmaf(cf.y, q.y, ae0b);
                av1a = fmaf(cf.x, q.z, av1a); av1b = fmaf(cf.y, q.z, av1b);
                ae1a = fmaf(cf.x, q.w, ae1a); ae1b = fmaf(cf.y, q.w, ae1b);
            }
            if (qr) {
                spartA[((qr - 1) << 7) + cp] = make_float4(av0a, ae0a, av1a, ae1a);
                spartB[((qr - 1) << 7) + cp] = make_float4(av0b, ae0b, av1b, ae1b);
            }
            __syncthreads();                                    // B4

            float v0a = 0, v0b = 0, v1a = 0, v1b = 0, m0 = 0, m1 = 0;
            if (qr == 0) {
                #pragma unroll
                for (int t = 0; t < 3; t++) {
                    const float4 pa = spartA[(t << 7) + cp];
                    const float4 pb = spartB[(t << 7) + cp];
                    av0a += pa.x; ae0a += pa.y; av1a += pa.z; ae1a += pa.w;
                    av0b += pb.x; ae0b += pb.y; av1b += pb.z; ae1b += pb.w;
                }
                const float2 ln0 = *reinterpret_cast<const float2*>(snu0 + 2 * cp);
                const float2 ln1 = *reinterpret_cast<const float2*>(snu1 + 2 * cp);
                const float mue0 = (it == 0) ? cmin : sred0[9];
                const float mue1 = (it == 0) ? cmin : sred1[9];
                v0a = ln0.x - (mue0 - cmin) - EPSV * __logf(av0a);
                v0b = ln0.y - (mue0 - cmin) - EPSV * __logf(av0b);
                v1a = ln1.x - (mue1 - cmin) - EPSV * __logf(av1a);
                v1b = ln1.y - (mue1 - cmin) - EPSV * __logf(av1b);
                m0 = fmaxf(v0a, v0b);
                m1 = fmaxf(v1a, v1b);
                #pragma unroll
                for (int o = 16; o; o >>= 1) {
                    m0 = fmaxf(m0, __shfl_xor_sync(0xFFFFFFFFu, m0, o));
                    m1 = fmaxf(m1, __shfl_xor_sync(0xFFFFFFFFu, m1, o));
                }
                if (l == 0) { sred0[w] = m0; sred1[w] = m1; }
            }
            __syncthreads();                                    // B5

            if (qr == 0) {
                m0 = fmaxf(fmaxf(sred0[0], sred0[1]), fmaxf(sred0[2], sred0[3]));
                m1 = fmaxf(fmaxf(sred1[0], sred1[1]), fmaxf(sred1[2], sred1[3]));
                if (active0) {
                    const float e0a = __expf((v0a - m0) * INV_EPS);
                    const float e0b = __expf((v0b - m0) * INV_EPS);
                    *reinterpret_cast<float2*>(sm + O_SEV + 2 * cp)
                        = make_float2(e0a, e0b);
                    if (tid == 0) sred0[10] = m0;
                    if (last0) {
                        const float mue0 = (it == 0) ? cmin : sred0[9];
                        const float sc = __expf((mue0 + m0 - cmin) * INV_EPS);
                        *reinterpret_cast<float2*>(out + s0 * N_DIM + 2 * cp)
                            = make_float2(sc * e0a * ae0a, sc * e0b * ae0b);
                    }
                }
                if (active1) {
                    const float e1a = __expf((v1a - m1) * INV_EPS);
                    const float e1b = __expf((v1b - m1) * INV_EPS);
                    *reinterpret_cast<float2*>(sm + O_SEV + 256 + 2 * cp)
                        = make_float2(e1a, e1b);
                    if (tid == 0) sred1[10] = m1;
                    if (last1) {
                        const float mue1 = (it == 0) ? cmin : sred1[9];
                        const float sc = __expf((mue1 + m1 - cmin) * INV_EPS);
                        *reinterpret_cast<float2*>(out + s1 * N_DIM + 2 * cp)
                            = make_float2(sc * e1a * ae1a, sc * e1b * ae1b);
                    }
                }
            }
            __syncthreads();                                    // B6
        }

        if (last0) active0 = false;
        if (last1) active1 = false;
        if (!active0 && !active1) break;
    }
}

// ---------------------------------------------------------------------------
// Launch
// ---------------------------------------------------------------------------
extern "C" void kernel_launch(void* const* d_in, const int* in_sizes, int n_in,
                              void* d_out, int out_size) {
    const float* mu = nullptr;
    const float* nu = nullptr;
    const float* C  = nullptr;
    for (int i = 0; i < n_in; ++i) {
        if (in_sizes[i] == S_TOT * B_DIM)      mu = (const float*)d_in[i];
        else if (in_sizes[i] == S_TOT * N_DIM) nu = (const float*)d_in[i];
        else if (in_sizes[i] == B_DIM * N_DIM) C  = (const float*)d_in[i];
    }
    float* out = (float*)d_out;

    const int smem_bytes = SMEM_FLOATS * sizeof(float);   // ~50.6 KB -> 4 blk/SM
    cudaFuncSetAttribute(ot_main_kernel,
                         cudaFuncAttributeMaxDynamicSharedMemorySize, smem_bytes);

    ot_init_kernel<<<16, 256>>>(C);
    ot_main_kernel<<<S_TOT / 2, THREADS, smem_bytes>>>(mu, nu, out);
}

// round 9
// speedup vs baseline: 1.6490x; 1.0307x over previous
#include <cuda_runtime.h>
#include <cuda_fp16.h>

#define S_TOT 2048
#define B_DIM 64
#define N_DIM 256
#define EPSV 0.01f
#define INV_EPS 100.0f
#define THRESH 0.1f
#define MAX_ITER 100
#define LOG_EPS 1e-8f
#define THREADS 512

// E0_ij = exp((Cmin - C_ij)/eps) in fp16; row sums (of fp16 values) in fp32.
__device__ __align__(16) __half g_E0h[B_DIM * N_DIM];
__device__ float g_logS[B_DIM];
__device__ float g_invS[B_DIM];
__device__ float g_Cmin;

// ---------------------------------------------------------------------------
// Init: 16 blocks x 256 threads. Every block redundantly computes cmin
// (identical deterministic reduction); block b builds rows 4b..4b+3.
// ---------------------------------------------------------------------------
__global__ void __launch_bounds__(256) ot_init_kernel(const float* __restrict__ C) {
    __shared__ float sred[9];
    const int tid = threadIdx.x, l = tid & 31, w = tid >> 5;

    float mn = 3.402823466e38f;
    const float4* C4 = reinterpret_cast<const float4*>(C);
    #pragma unroll
    for (int k = 0; k < 16; k++) {
        const float4 c = C4[tid + 256 * k];
        mn = fminf(mn, fminf(fminf(c.x, c.y), fminf(c.z, c.w)));
    }
    #pragma unroll
    for (int o = 16; o; o >>= 1)
        mn = fminf(mn, __shfl_xor_sync(0xFFFFFFFFu, mn, o));
    if (l == 0) sred[w] = mn;
    __syncthreads();
    if (tid == 0) {
        float t = sred[0];
        #pragma unroll
        for (int k = 1; k < 8; k++) t = fminf(t, sred[k]);
        sred[8] = t;
        if (blockIdx.x == 0) g_Cmin = t;
    }
    __syncthreads();
    const float cmin = sred[8];

    #pragma unroll
    for (int rr = 0; rr < 4; rr++) {
        const int row = blockIdx.x * 4 + rr;
        const float val = __expf((cmin - C[(row << 8) + tid]) * INV_EPS);
        const __half hv = __float2half_rn(val);
        g_E0h[(row << 8) + tid] = hv;
        float f = __half2float(hv);
        #pragma unroll
        for (int o = 16; o; o >>= 1)
            f += __shfl_xor_sync(0xFFFFFFFFu, f, o);
        __syncthreads();
        if (l == 0) sred[w] = f;
        __syncthreads();
        if (tid == 0) {
            float s = 0.0f;
            #pragma unroll
            for (int k = 0; k < 8; k++) s += sred[k];
            g_logS[row] = __logf(s);
            g_invS[row] = 1.0f / s;
        }
    }
}

// smem layout (float offsets); E0h occupies floats [0,8192) as half[16384].
#define O_EUWT  8192    // float4[64]: (eu0, wt0, eu1, wt1)
#define O_SPART 8448    // spartA float4[384] @8448, spartB float4[384] @9984
#define O_SDU   8448    // alias (temporally disjoint)
#define O_SNU   11520   // snu0 [256], snu1 [256]
#define O_SEV   12032   // sev0 [256], sev1 [256]
#define O_SU    12544   // 2 x 64
#define O_SLM   12672
#define O_SMU   12800
#define O_SRED  12928   // 2 x 16: [0..3]=mv partials, [8]=err, [9]=m_u, [10]=m_v
#define SMEM_FLOATS 12960

// ---------------------------------------------------------------------------
// Main: 2 samples/block, 512 threads, fp16 E0 in shared, 3 blocks/SM
// (regs ~40 -- the proven sweet spot; (512,4) forced 32 regs and regressed).
//  - it=0 u-update from precomputed row sums.
//  - u-pass (it>=1): per-sample; warps 0-7 sample0, 8-15 sample1.
//  - v-pass: thread (qr = row-quarter, cp = col-pair). LIGHT path when no
//    sample finishes this iter (av-only, single-float4 exchange); FULL path
//    (av+ae) otherwise, outputs written in place on the last iteration.
// ---------------------------------------------------------------------------
extern "C" __global__ void __launch_bounds__(THREADS, 3)
ot_main_kernel(const float* __restrict__ mu,
               const float* __restrict__ nu,
               float* __restrict__ out) {
    extern __shared__ float sm[];
    __half* sE0h = reinterpret_cast<__half*>(sm);

    const int tid = threadIdx.x;
    const int h   = tid >> 8;          // sample slot (u/euwt mapping)
    const int col = tid & 255;
    const int l   = tid & 31;
    const int w   = tid >> 5;          // 0..15
    const int ws  = w & 7;
    const int qr  = tid >> 7;          // row-quarter (v mapping)
    const int cp  = tid & 127;         // col-pair

    float* snu0   = sm + O_SNU;
    float* snu1   = sm + O_SNU + 256;
    float* sev_h  = sm + O_SEV + (h << 8);
    float* su_h   = sm + O_SU  + (h << 6);
    float* slm_h  = sm + O_SLM + (h << 6);
    float* smu_h  = sm + O_SMU + (h << 6);
    float* sred0  = sm + O_SRED;
    float* sred1  = sm + O_SRED + 16;
    float* sred_h = sm + O_SRED + (h << 4);
    float* sdu_h  = sm + O_SDU + (h << 6);
    float4* spartA = reinterpret_cast<float4*>(sm + O_SPART);
    float4* spartB = spartA + 384;

    const int s0 = blockIdx.x * 2, s1 = s0 + 1, s_h = s0 + h;

    // ---- stage E0h (32KB, uint4) ----
    {
        const uint4* g4 = reinterpret_cast<const uint4*>(g_E0h);
        uint4* s4 = reinterpret_cast<uint4*>(sE0h);
        #pragma unroll
        for (int k = 0; k < 4; k++)
            s4[tid + THREADS * k] = g4[tid + THREADS * k];
    }
    if (col < B_DIM) {
        const float m = mu[s_h * B_DIM + col];
        smu_h[col] = m;
        slm_h[col] = __logf(m + LOG_EPS);
    }
    sm[O_SNU + (h << 8) + col] = EPSV * __logf(nu[s_h * N_DIM + col] + LOG_EPS);
    if (tid == 0) { sred0[10] = 0.0f; sred1[10] = 0.0f; }
    const float cmin = g_Cmin;
    __syncthreads();

    bool active0 = true, active1 = true;

    for (int it = 0; it < MAX_ITER; ++it) {
        const bool act_h = h ? active1 : active0;

        // ---- u phase ----
        if (it == 0) {
            if (col < B_DIM) {
                const float u1 = EPSV * (slm_h[col] - g_logS[col]) + cmin;
                su_h[col]  = u1;
                sdu_h[col] = fabsf(u1);
            }
        } else if (act_h) {
            const float m_v_h = sred_h[10];
            const float4 evA = reinterpret_cast<const float4*>(sev_h)[2 * l];
            const float4 evB = reinterpret_cast<const float4*>(sev_h)[2 * l + 1];
            #pragma unroll
            for (int r = 0; r < 8; ++r) {
                const int row = (ws << 3) + r;
                const int4 hv = reinterpret_cast<const int4*>(sE0h + (row << 8))[l];
                const __half2* hp = reinterpret_cast<const __half2*>(&hv);
                const float2 f0 = __half22float2(hp[0]);
                const float2 f1 = __half22float2(hp[1]);
                const float2 f2 = __half22float2(hp[2]);
                const float2 f3 = __half22float2(hp[3]);
                float p = f0.x * evA.x + f0.y * evA.y + f1.x * evA.z + f1.y * evA.w
                        + f2.x * evB.x + f2.y * evB.y + f3.x * evB.z + f3.y * evB.w;
                #pragma unroll
                for (int o = 16; o; o >>= 1)
                    p += __shfl_xor_sync(0xFFFFFFFFu, p, o);
                if (l == r) {
                    const float unew = EPSV * slm_h[row] - (m_v_h - cmin)
                                     - EPSV * __logf(p);
                    sdu_h[row] = fabsf(unew - su_h[row]);
                    su_h[row]  = unew;
                }
            }
        }
        __syncthreads();                                        // B1

        // ---- err / m_u reduce (warps 0 and 8) ----
        if (ws == 0) {
            float d  = sdu_h[l] + sdu_h[l + 32];
            float um = fmaxf(su_h[l], su_h[l + 32]);
            #pragma unroll
            for (int o = 16; o; o >>= 1) {
                d  += __shfl_xor_sync(0xFFFFFFFFu, d, o);
                um  = fmaxf(um, __shfl_xor_sync(0xFFFFFFFFu, um, o));
            }
            if (l == 0) { sred_h[8] = d; sred_h[9] = um; }
        }
        __syncthreads();                                        // B2
        const float err0 = sred0[8], err1 = sred1[8];
        const bool last0 = active0 && (err0 < THRESH || it == MAX_ITER - 1);
        const bool last1 = active1 && (err1 < THRESH || it == MAX_ITER - 1);
        const bool anyLast = last0 || last1;

        // ---- euwt: (eu0, wt0, eu1, wt1) per row ----
        if (col < B_DIM && act_h) {
            const float eu = (it == 0)
                ? (smu_h[col] + LOG_EPS) * g_invS[col]
                : __expf((su_h[col] - sred_h[9]) * INV_EPS);
            float* qp = sm + O_EUWT + (col << 2);
            qp[2 * h]     = eu;
            qp[2 * h + 1] = eu * smu_h[col];
        }
        __syncthreads();                                        // B3

        const __half2* cph = reinterpret_cast<const __half2*>(sE0h)
                           + (qr << 11) + cp;
        const float4* qw = reinterpret_cast<const float4*>(sm + O_EUWT) + (qr << 4);

        if (!anyLast) {
            // ===== LIGHT v-pass: av only (4 FMAs/row), 1-float4 exchange =====
            float av0a = 0, av0b = 0, av1a = 0, av1b = 0;
            #pragma unroll
            for (int i = 0; i < 16; i++) {
                const float2 cf = __half22float2(cph[i << 7]);
                const float4 q  = qw[i];
                av0a = fmaf(cf.x, q.x, av0a); av0b = fmaf(cf.y, q.x, av0b);
                av1a = fmaf(cf.x, q.z, av1a); av1b = fmaf(cf.y, q.z, av1b);
            }
            if (qr) spartA[((qr - 1) << 7) + cp] = make_float4(av0a, av0b, av1a, av1b);
            __syncthreads();                                    // B4
            float v0a = 0, v0b = 0, v1a = 0, v1b = 0, m0 = 0, m1 = 0;
            if (qr == 0) {
                #pragma unroll
                for (int t = 0; t < 3; t++) {
                    const float4 pa = spartA[(t << 7) + cp];
                    av0a += pa.x; av0b += pa.y; av1a += pa.z; av1b += pa.w;
                }
                const float2 ln0 = *reinterpret_cast<const float2*>(snu0 + 2 * cp);
                const float2 ln1 = *reinterpret_cast<const float2*>(snu1 + 2 * cp);
                const float mue0 = (it == 0) ? cmin : sred0[9];
                const float mue1 = (it == 0) ? cmin : sred1[9];
                v0a = ln0.x - (mue0 - cmin) - EPSV * __logf(av0a);
                v0b = ln0.y - (mue0 - cmin) - EPSV * __logf(av0b);
                v1a = ln1.x - (mue1 - cmin) - EPSV * __logf(av1a);
                v1b = ln1.y - (mue1 - cmin) - EPSV * __logf(av1b);
                m0 = fmaxf(v0a, v0b);
                m1 = fmaxf(v1a, v1b);
                #pragma unroll
                for (int o = 16; o; o >>= 1) {
                    m0 = fmaxf(m0, __shfl_xor_sync(0xFFFFFFFFu, m0, o));
                    m1 = fmaxf(m1, __shfl_xor_sync(0xFFFFFFFFu, m1, o));
                }
                if (l == 0) { sred0[w] = m0; sred1[w] = m1; }   // w = 0..3
            }
            __syncthreads();                                    // B5
            if (qr == 0) {
                m0 = fmaxf(fmaxf(sred0[0], sred0[1]), fmaxf(sred0[2], sred0[3]));
                m1 = fmaxf(fmaxf(sred1[0], sred1[1]), fmaxf(sred1[2], sred1[3]));
                if (active0) {
                    *reinterpret_cast<float2*>(sm + O_SEV + 2 * cp)
                        = make_float2(__expf((v0a - m0) * INV_EPS),
                                      __expf((v0b - m0) * INV_EPS));
                    if (tid == 0) sred0[10] = m0;
                }
                if (active1) {
                    *reinterpret_cast<float2*>(sm + O_SEV + 256 + 2 * cp)
                        = make_float2(__expf((v1a - m1) * INV_EPS),
                                      __expf((v1b - m1) * INV_EPS));
                    if (tid == 0) sred1[10] = m1;
                }
            }
            __syncthreads();                                    // B6
        } else {
            // ===== FULL v-pass: av+ae, outputs written on last iteration =====
            float av0a = 0, av0b = 0, ae0a = 0, ae0b = 0;
            float av1a = 0, av1b = 0, ae1a = 0, ae1b = 0;
            #pragma unroll
            for (int i = 0; i < 16; i++) {
                const float2 cf = __half22float2(cph[i << 7]);
                const float4 q  = qw[i];
                av0a = fmaf(cf.x, q.x, av0a); av0b = fmaf(cf.y, q.x, av0b);
                ae0a = fmaf(cf.x, q.y, ae0a); ae0b = fmaf(cf.y, q.y, ae0b);
                av1a = fmaf(cf.x, q.z, av1a); av1b = fmaf(cf.y, q.z, av1b);
                ae1a = fmaf(cf.x, q.w, ae1a); ae1b = fmaf(cf.y, q.w, ae1b);
            }
            if (qr) {
                spartA[((qr - 1) << 7) + cp] = make_float4(av0a, ae0a, av1a, ae1a);
                spartB[((qr - 1) << 7) + cp] = make_float4(av0b, ae0b, av1b, ae1b);
            }
            __syncthreads();                                    // B4

            float v0a = 0, v0b = 0, v1a = 0, v1b = 0, m0 = 0, m1 = 0;
            if (qr == 0) {
                #pragma unroll
                for (int t = 0; t < 3; t++) {
                    const float4 pa = spartA[(t << 7) + cp];
                    const float4 pb = spartB[(t << 7) + cp];
                    av0a += pa.x; ae0a += pa.y; av1a += pa.z; ae1a += pa.w;
                    av0b += pb.x; ae0b += pb.y; av1b += pb.z; ae1b += pb.w;
                }
                const float2 ln0 = *reinterpret_cast<const float2*>(snu0 + 2 * cp);
                const float2 ln1 = *reinterpret_cast<const float2*>(snu1 + 2 * cp);
                const float mue0 = (it == 0) ? cmin : sred0[9];
                const float mue1 = (it == 0) ? cmin : sred1[9];
                v0a = ln0.x - (mue0 - cmin) - EPSV * __logf(av0a);
                v0b = ln0.y - (mue0 - cmin) - EPSV * __logf(av0b);
                v1a = ln1.x - (mue1 - cmin) - EPSV * __logf(av1a);
                v1b = ln1.y - (mue1 - cmin) - EPSV * __logf(av1b);
                m0 = fmaxf(v0a, v0b);
                m1 = fmaxf(v1a, v1b);
                #pragma unroll
                for (int o = 16; o; o >>= 1) {
                    m0 = fmaxf(m0, __shfl_xor_sync(0xFFFFFFFFu, m0, o));
                    m1 = fmaxf(m1, __shfl_xor_sync(0xFFFFFFFFu, m1, o));
                }
                if (l == 0) { sred0[w] = m0; sred1[w] = m1; }
            }
            __syncthreads();                                    // B5

            if (qr == 0) {
                m0 = fmaxf(fmaxf(sred0[0], sred0[1]), fmaxf(sred0[2], sred0[3]));
                m1 = fmaxf(fmaxf(sred1[0], sred1[1]), fmaxf(sred1[2], sred1[3]));
                if (active0) {
                    const float e0a = __expf((v0a - m0) * INV_EPS);
                    const float e0b = __expf((v0b - m0) * INV_EPS);
                    *reinterpret_cast<float2*>(sm + O_SEV + 2 * cp)
                        = make_float2(e0a, e0b);
                    if (tid == 0) sred0[10] = m0;
                    if (last0) {
                        const float mue0 = (it == 0) ? cmin : sred0[9];
                        const float sc = __expf((mue0 + m0 - cmin) * INV_EPS);
                        *reinterpret_cast<float2*>(out + s0 * N_DIM + 2 * cp)
                            = make_float2(sc * e0a * ae0a, sc * e0b * ae0b);
                    }
                }
                if (active1) {
                    const float e1a = __expf((v1a - m1) * INV_EPS);
                    const float e1b = __expf((v1b - m1) * INV_EPS);
                    *reinterpret_cast<float2*>(sm + O_SEV + 256 + 2 * cp)
                        = make_float2(e1a, e1b);
                    if (tid == 0) sred1[10] = m1;
                    if (last1) {
                        const float mue1 = (it == 0) ? cmin : sred1[9];
                        const float sc = __expf((mue1 + m1 - cmin) * INV_EPS);
                        *reinterpret_cast<float2*>(out + s1 * N_DIM + 2 * cp)
                            = make_float2(sc * e1a * ae1a, sc * e1b * ae1b);
                    }
                }
            }
            __syncthreads();                                    // B6
        }

        if (last0) active0 = false;
        if (last1) active1 = false;
        if (!active0 && !active1) break;
    }
}

// ---------------------------------------------------------------------------
// Launch
// ---------------------------------------------------------------------------
extern "C" void kernel_launch(void* const* d_in, const int* in_sizes, int n_in,
                              void* d_out, int out_size) {
    const float* mu = nullptr;
    const float* nu = nullptr;
    const float* C  = nullptr;
    for (int i = 0; i < n_in; ++i) {
        if (in_sizes[i] == S_TOT * B_DIM)      mu = (const float*)d_in[i];
        else if (in_sizes[i] == S_TOT * N_DIM) nu = (const float*)d_in[i];
        else if (in_sizes[i] == B_DIM * N_DIM) C  = (const float*)d_in[i];
    }
    float* out = (float*)d_out;

    const int smem_bytes = SMEM_FLOATS * sizeof(float);   // ~50.6 KB, 3 blk/SM
    cudaFuncSetAttribute(ot_main_kernel,
                         cudaFuncAttributeMaxDynamicSharedMemorySize, smem_bytes);

    ot_init_kernel<<<16, 256>>>(C);
    ot_main_kernel<<<S_TOT / 2, THREADS, smem_bytes>>>(mu, nu, out);
}